// round 2
// baseline (speedup 1.0000x reference)
#include <cuda_runtime.h>
#include <cuda_bf16.h>
#include <math.h>
#include <stdint.h>

// Problem constants
#define NQ     12
#define DIMN   4096
#define HALFN  2048
#define NBATCH 2048
#define MROWS  (2 * NBATCH)   // stacked re/im rows = 4096

// ---------------------------------------------------------------------------
// Scratch (__device__ globals per harness rules)
// Stacked layout: rows [0,2048) = real part, rows [2048,4096) = imag part.
// ---------------------------------------------------------------------------
__device__ __nv_bfloat16 g_Ah[(size_t)MROWS * DIMN];   // V hi, later W hi
__device__ __nv_bfloat16 g_Al[(size_t)MROWS * DIMN];   // V lo, later W lo
__device__ __nv_bfloat16 g_Eh[(size_t)DIMN * DIMN];
__device__ __nv_bfloat16 g_El[(size_t)DIMN * DIMN];
__device__ __nv_bfloat16 g_Gh[(size_t)HALFN * DIMN];   // G = r00*Etop + r01*Ebot
__device__ __nv_bfloat16 g_Gl[(size_t)HALFN * DIMN];
__device__ float g_W[(size_t)MROWS * DIMN];            // GEMM1 output (fp32)
__device__ float g_Y[(size_t)MROWS * HALFN];           // GEMM2 output (fp32)
__device__ float g_gates[NQ * 8];

__device__ __forceinline__ void split1(float x, __nv_bfloat16& h, __nv_bfloat16& l) {
    h = __float2bfloat16(x);
    l = __float2bfloat16(x - __bfloat162float(h));
}

// ---------------------------------------------------------------------------
// prep: per-qubit gate matrices  mats[q] = Rx(w[3+q]) @ Rz(w[15+q])
// ---------------------------------------------------------------------------
__global__ void prep_kernel(const float* __restrict__ w) {
    int q = threadIdx.x;
    if (q < NQ) {
        float tx = 0.5f * w[3 + q];
        float tz = 0.5f * w[3 + NQ + q];
        float s, c, sz, cz;
        sincosf(tx, &s, &c);
        sincosf(tz, &sz, &cz);
        float* m = g_gates + q * 8;
        m[0] =  c * cz;  m[1] = -c * sz;
        m[2] =  s * sz;  m[3] = -s * cz;
        m[4] = -s * sz;  m[5] = -s * cz;
        m[6] =  c * cz;  m[7] =  c * sz;
    }
}

// ---------------------------------------------------------------------------
// split_EG: one pass over E producing Ehi/Elo (full) and Ghi/Glo (half).
// G = r00 * E[0:2048,:] + r01 * E[2048:4096,:]; rot angle = (w0+w1+w2)/2.
// Processes float4 chunks over the top half; bottom half read in same pass.
// ---------------------------------------------------------------------------
__global__ __launch_bounds__(256) void split_EG(const float* __restrict__ E,
                                                const float* __restrict__ w) {
    float th  = 0.5f * (w[0] + w[1] + w[2]);
    float r00 = cosf(th);
    float r01 = -sinf(th);
    size_t i = (size_t)blockIdx.x * blockDim.x + threadIdx.x;   // float4 idx in top half
    const size_t HOFF4 = (size_t)HALFN * DIMN / 4;
    const float4* E4 = (const float4*)E;
    float4 a = E4[i];          // top
    float4 b = E4[i + HOFF4];  // bottom

    __nv_bfloat162* Eh2 = (__nv_bfloat162*)g_Eh;
    __nv_bfloat162* El2 = (__nv_bfloat162*)g_El;
    __nv_bfloat162* Gh2 = (__nv_bfloat162*)g_Gh;
    __nv_bfloat162* Gl2 = (__nv_bfloat162*)g_Gl;

    float va[4] = {a.x, a.y, a.z, a.w};
    float vb[4] = {b.x, b.y, b.z, b.w};
    __nv_bfloat16 eh[8], el[8], gh[4], gl[4];
    #pragma unroll
    for (int k = 0; k < 4; ++k) {
        split1(va[k], eh[k],     el[k]);
        split1(vb[k], eh[4 + k], el[4 + k]);
        float g = r00 * va[k] + r01 * vb[k];
        split1(g, gh[k], gl[k]);
    }
    size_t t2 = 2 * i;                   // bf16x2 index, top
    size_t b2 = 2 * (i + HOFF4);         // bottom
    Eh2[t2]     = __nv_bfloat162(eh[0], eh[1]);
    Eh2[t2 + 1] = __nv_bfloat162(eh[2], eh[3]);
    El2[t2]     = __nv_bfloat162(el[0], el[1]);
    El2[t2 + 1] = __nv_bfloat162(el[2], el[3]);
    Eh2[b2]     = __nv_bfloat162(eh[4], eh[5]);
    Eh2[b2 + 1] = __nv_bfloat162(eh[6], eh[7]);
    El2[b2]     = __nv_bfloat162(el[4], el[5]);
    El2[b2 + 1] = __nv_bfloat162(el[6], el[7]);
    Gh2[t2]     = __nv_bfloat162(gh[0], gh[1]);
    Gh2[t2 + 1] = __nv_bfloat162(gh[2], gh[3]);
    Gl2[t2]     = __nv_bfloat162(gl[0], gl[1]);
    Gl2[t2 + 1] = __nv_bfloat162(gl[2], gl[3]);
}

// ---------------------------------------------------------------------------
// encode: v[b,j] = prod_q (bit==0 ? a_q : b_q); writes split bf16 directly.
// ---------------------------------------------------------------------------
__global__ __launch_bounds__(256) void encode_kernel(const float* __restrict__ inputs) {
    __shared__ float ar[NQ], ai[NQ], br[NQ], bi[NQ];
    const int b = blockIdx.x;
    if (threadIdx.x < NQ) {
        float x = inputs[b * NQ + threadIdx.x];
        float sy, cy, sz, cz;
        sincosf(0.5f * x, &sy, &cy);
        sincosf(0.5f * x * x, &sz, &cz);
        ar[threadIdx.x] = cy * cz;  ai[threadIdx.x] = -cy * sz;
        br[threadIdx.x] = sy * cz;  bi[threadIdx.x] =  sy * sz;
    }
    __syncthreads();
    for (int j = threadIdx.x; j < DIMN; j += blockDim.x) {
        float pr = 1.f, pi = 0.f;
        #pragma unroll
        for (int q = 0; q < NQ; ++q) {
            int bit = (j >> (NQ - 1 - q)) & 1;
            float cr = bit ? br[q] : ar[q];
            float ci = bit ? bi[q] : ai[q];
            float nr = pr * cr - pi * ci;
            float ni = pr * ci + pi * cr;
            pr = nr; pi = ni;
        }
        __nv_bfloat16 h, l;
        split1(pr, h, l);
        g_Ah[(size_t)b * DIMN + j] = h;
        g_Al[(size_t)b * DIMN + j] = l;
        split1(pi, h, l);
        g_Ah[(size_t)(NBATCH + b) * DIMN + j] = h;
        g_Al[(size_t)(NBATCH + b) * DIMN + j] = l;
    }
}

// ---------------------------------------------------------------------------
// Split-bf16 NT GEMM:  C[M,N] = (Ah+Al)[M,K] * ((Bh+Bl)[N,K])^T  (row-major, K contig)
// acc += Ah*Bh + Ah*Bl + Al*Bh   (lo*lo dropped)
// 128x128x16 tiles, 8 warps (warp tile 64x32), cp.async double buffer.
// ---------------------------------------------------------------------------
#define BM 128
#define BN 128
#define BK 16
#define ASTR 12   // row stride in uint32 (8 used + 4 pad): conflict-free frag loads

__device__ __forceinline__ unsigned sptr(const void* p) {
    return (unsigned)__cvta_generic_to_shared(p);
}

__device__ __forceinline__ void cpa16(uint32_t* s, const __nv_bfloat16* g) {
    asm volatile("cp.async.cg.shared.global [%0], [%1], 16;\n"
                 :: "r"(sptr(s)), "l"(g));
}

__device__ __forceinline__ void mma16(float c[4], const unsigned a[4], const unsigned b[2]) {
    asm volatile(
        "mma.sync.aligned.m16n8k16.row.col.f32.bf16.bf16.f32 "
        "{%0,%1,%2,%3}, {%4,%5,%6,%7}, {%8,%9}, {%0,%1,%2,%3};\n"
        : "+f"(c[0]), "+f"(c[1]), "+f"(c[2]), "+f"(c[3])
        : "r"(a[0]), "r"(a[1]), "r"(a[2]), "r"(a[3]), "r"(b[0]), "r"(b[1]));
}

__device__ __forceinline__ void gemm_split_body(const __nv_bfloat16* __restrict__ Ah,
                                                const __nv_bfloat16* __restrict__ Al,
                                                const __nv_bfloat16* __restrict__ Bh,
                                                const __nv_bfloat16* __restrict__ Bl,
                                                float* __restrict__ C,
                                                int N, int K) {
    __shared__ uint32_t sAh[2][BM * ASTR];
    __shared__ uint32_t sAl[2][BM * ASTR];
    __shared__ uint32_t sBh[2][BN * ASTR];
    __shared__ uint32_t sBl[2][BN * ASTR];

    const int tid  = threadIdx.x;
    const int warp = tid >> 5;
    const int lane = tid & 31;
    const int wm = (warp & 1) * 64;
    const int wn = (warp >> 1) * 32;
    const int g  = lane >> 2;
    const int t4 = lane & 3;

    const __nv_bfloat16* Abh = Ah + (size_t)blockIdx.y * BM * K;
    const __nv_bfloat16* Abl = Al + (size_t)blockIdx.y * BM * K;
    const __nv_bfloat16* Bbh = Bh + (size_t)blockIdx.x * BN * K;
    const __nv_bfloat16* Bbl = Bl + (size_t)blockIdx.x * BN * K;

    const int lrow  = tid >> 1;          // 0..127
    const int lhalf = (tid & 1) * 8;     // bf16 offset 0 or 8 within BK
    const int scol  = (tid & 1) * 4;     // uint32 offset 0 or 4

    float acc[4][4][4];
    #pragma unroll
    for (int i = 0; i < 4; ++i)
        #pragma unroll
        for (int j = 0; j < 4; ++j)
            #pragma unroll
            for (int k = 0; k < 4; ++k) acc[i][j][k] = 0.f;

    const int nk = K / BK;

    // stage 0 loads
    {
        int k0 = 0;
        cpa16(&sAh[0][lrow * ASTR + scol], Abh + (size_t)lrow * K + k0 + lhalf);
        cpa16(&sAl[0][lrow * ASTR + scol], Abl + (size_t)lrow * K + k0 + lhalf);
        cpa16(&sBh[0][lrow * ASTR + scol], Bbh + (size_t)lrow * K + k0 + lhalf);
        cpa16(&sBl[0][lrow * ASTR + scol], Bbl + (size_t)lrow * K + k0 + lhalf);
        asm volatile("cp.async.commit_group;\n");
    }

    for (int t = 0; t < nk; ++t) {
        asm volatile("cp.async.wait_group 0;\n");
        __syncthreads();
        if (t + 1 < nk) {
            int k0 = (t + 1) * BK;
            int s  = (t + 1) & 1;
            cpa16(&sAh[s][lrow * ASTR + scol], Abh + (size_t)lrow * K + k0 + lhalf);
            cpa16(&sAl[s][lrow * ASTR + scol], Abl + (size_t)lrow * K + k0 + lhalf);
            cpa16(&sBh[s][lrow * ASTR + scol], Bbh + (size_t)lrow * K + k0 + lhalf);
            cpa16(&sBl[s][lrow * ASTR + scol], Bbl + (size_t)lrow * K + k0 + lhalf);
            asm volatile("cp.async.commit_group;\n");
        }

        const uint32_t* ah = sAh[t & 1];
        const uint32_t* al = sAl[t & 1];
        const uint32_t* bh = sBh[t & 1];
        const uint32_t* bl = sBl[t & 1];

        unsigned afh[4][4], afl[4][4], bfh[4][2], bfl[4][2];
        #pragma unroll
        for (int mt = 0; mt < 4; ++mt) {
            int r = wm + mt * 16 + g;
            afh[mt][0] = ah[(r)     * ASTR + t4];
            afh[mt][1] = ah[(r + 8) * ASTR + t4];
            afh[mt][2] = ah[(r)     * ASTR + t4 + 4];
            afh[mt][3] = ah[(r + 8) * ASTR + t4 + 4];
            afl[mt][0] = al[(r)     * ASTR + t4];
            afl[mt][1] = al[(r + 8) * ASTR + t4];
            afl[mt][2] = al[(r)     * ASTR + t4 + 4];
            afl[mt][3] = al[(r + 8) * ASTR + t4 + 4];
        }
        #pragma unroll
        for (int nt = 0; nt < 4; ++nt) {
            int r = wn + nt * 8 + g;
            bfh[nt][0] = bh[r * ASTR + t4];
            bfh[nt][1] = bh[r * ASTR + t4 + 4];
            bfl[nt][0] = bl[r * ASTR + t4];
            bfl[nt][1] = bl[r * ASTR + t4 + 4];
        }
        #pragma unroll
        for (int mt = 0; mt < 4; ++mt)
            #pragma unroll
            for (int nt = 0; nt < 4; ++nt) {
                mma16(acc[mt][nt], afh[mt], bfh[nt]);
                mma16(acc[mt][nt], afh[mt], bfl[nt]);
                mma16(acc[mt][nt], afl[mt], bfh[nt]);
            }
        __syncthreads();
    }

    // epilogue
    #pragma unroll
    for (int mt = 0; mt < 4; ++mt) {
        int row = blockIdx.y * BM + wm + mt * 16 + g;
        #pragma unroll
        for (int nt = 0; nt < 4; ++nt) {
            int col = blockIdx.x * BN + wn + nt * 8 + 2 * t4;
            float2 v0 = make_float2(acc[mt][nt][0], acc[mt][nt][1]);
            float2 v1 = make_float2(acc[mt][nt][2], acc[mt][nt][3]);
            *(float2*)&C[(size_t)row * N + col]       = v0;
            *(float2*)&C[(size_t)(row + 8) * N + col] = v1;
        }
    }
}

__global__ __launch_bounds__(256) void gemm1_kernel() {
    gemm_split_body(g_Ah, g_Al, g_Eh, g_El, g_W, DIMN, DIMN);
}
__global__ __launch_bounds__(256) void gemm2_kernel() {
    gemm_split_body(g_Ah, g_Al, g_Gh, g_Gl, g_Y, HALFN, DIMN);
}

// ---------------------------------------------------------------------------
// gate sweep: apply 12 complex 2x2 gates per batch row in shared memory,
// then write split bf16 back into g_Ah/g_Al (V no longer needed).
// ---------------------------------------------------------------------------
__global__ __launch_bounds__(256) void gate_kernel() {
    __shared__ float wr[DIMN];
    __shared__ float wi[DIMN];
    const int b = blockIdx.x;
    const float* Wr = g_W + (size_t)b * DIMN;
    const float* Wi = g_W + (size_t)(NBATCH + b) * DIMN;

    for (int j = threadIdx.x * 4; j < DIMN; j += blockDim.x * 4) {
        *(float4*)&wr[j] = *(const float4*)&Wr[j];
        *(float4*)&wi[j] = *(const float4*)&Wi[j];
    }
    __syncthreads();

    #pragma unroll 1
    for (int q = 0; q < NQ; ++q) {
        const float* m = g_gates + q * 8;
        float m00r = m[0], m00i = m[1], m01r = m[2], m01i = m[3];
        float m10r = m[4], m10i = m[5], m11r = m[6], m11i = m[7];
        int p  = NQ - 1 - q;
        int st = 1 << p;
        for (int t = threadIdx.x; t < HALFN; t += blockDim.x) {
            int j0 = ((t >> p) << (p + 1)) | (t & (st - 1));
            int j1 = j0 + st;
            float w0r = wr[j0], w0i = wi[j0];
            float w1r = wr[j1], w1i = wi[j1];
            wr[j0] = m00r * w0r - m00i * w0i + m01r * w1r - m01i * w1i;
            wi[j0] = m00r * w0i + m00i * w0r + m01r * w1i + m01i * w1r;
            wr[j1] = m10r * w0r - m10i * w0i + m11r * w1r - m11i * w1i;
            wi[j1] = m10r * w0i + m10i * w0r + m11r * w1i + m11i * w1r;
        }
        __syncthreads();
    }

    for (int j = threadIdx.x; j < DIMN; j += blockDim.x) {
        __nv_bfloat16 h, l;
        split1(wr[j], h, l);
        g_Ah[(size_t)b * DIMN + j] = h;
        g_Al[(size_t)b * DIMN + j] = l;
        split1(wi[j], h, l);
        g_Ah[(size_t)(NBATCH + b) * DIMN + j] = h;
        g_Al[(size_t)(NBATCH + b) * DIMN + j] = l;
    }
}

// ---------------------------------------------------------------------------
// reduce: out[b] = sum_i Yr[b,i]^2 + Yi[b,i]^2
// ---------------------------------------------------------------------------
__global__ __launch_bounds__(256) void reduce_kernel(float* __restrict__ out) {
    const int b = blockIdx.x;
    const float* Yr = g_Y + (size_t)b * HALFN;
    const float* Yi = g_Y + (size_t)(NBATCH + b) * HALFN;
    float s = 0.f;
    for (int i = threadIdx.x; i < HALFN; i += blockDim.x) {
        float a = Yr[i], c = Yi[i];
        s += a * a + c * c;
    }
    #pragma unroll
    for (int o = 16; o > 0; o >>= 1) s += __shfl_xor_sync(0xffffffffu, s, o);
    __shared__ float red[8];
    if ((threadIdx.x & 31) == 0) red[threadIdx.x >> 5] = s;
    __syncthreads();
    if (threadIdx.x < 8) {
        s = red[threadIdx.x];
        #pragma unroll
        for (int o = 4; o > 0; o >>= 1) s += __shfl_xor_sync(0xffu, s, o);
        if (threadIdx.x == 0) out[b] = s;
    }
}

// ---------------------------------------------------------------------------
extern "C" void kernel_launch(void* const* d_in, const int* in_sizes, int n_in,
                              void* d_out, int out_size) {
    const float* inputs = (const float*)d_in[0];   // [2048,12]
    const float* weight = (const float*)d_in[1];   // [27]
    const float* E      = (const float*)d_in[2];   // [4096,4096]
    float* out          = (float*)d_out;           // [2048]

    prep_kernel<<<1, 32>>>(weight);
    split_EG<<<(HALFN * DIMN / 4) / 256, 256>>>(E, weight);
    encode_kernel<<<NBATCH, 256>>>(inputs);

    {
        dim3 grid(DIMN / BN, MROWS / BM);   // (32, 32)
        gemm1_kernel<<<grid, 256>>>();
    }
    gate_kernel<<<NBATCH, 256>>>();
    {
        dim3 grid(HALFN / BN, MROWS / BM);  // (16, 32)
        gemm2_kernel<<<grid, 256>>>();
    }
    reduce_kernel<<<NBATCH, 256>>>(out);
}

// round 5
// speedup vs baseline: 1.3292x; 1.3292x over previous
#include <cuda_runtime.h>
#include <cuda_bf16.h>
#include <math.h>
#include <stdint.h>

// Problem constants
#define NQ     12
#define DIMN   4096
#define HALFN  2048
#define NBATCH 2048
#define MROWS  (2 * NBATCH)   // stacked re/im rows = 4096
#define GK     4096           // GEMM K

// ---------------------------------------------------------------------------
// Scratch (__device__ globals per harness rules)
// ---------------------------------------------------------------------------
__device__ __nv_bfloat16 g_Ah[(size_t)MROWS * DIMN];   // V hi, later W hi
__device__ __nv_bfloat16 g_Al[(size_t)MROWS * DIMN];   // V lo, later W lo
__device__ __nv_bfloat16 g_Eh[(size_t)DIMN * DIMN];
__device__ __nv_bfloat16 g_El[(size_t)DIMN * DIMN];
__device__ __nv_bfloat16 g_Gh[(size_t)HALFN * DIMN];   // G = r00*Etop + r01*Ebot
__device__ __nv_bfloat16 g_Gl[(size_t)HALFN * DIMN];
__device__ float g_W[(size_t)MROWS * DIMN];            // GEMM1 output (fp32)
__device__ float g_Y[(size_t)MROWS * HALFN];           // GEMM2 output (fp32)
__device__ float g_gates[NQ * 8];

__device__ __forceinline__ void split1(float x, __nv_bfloat16& h, __nv_bfloat16& l) {
    h = __float2bfloat16(x);
    l = __float2bfloat16(x - __bfloat162float(h));
}

// ---------------------------------------------------------------------------
// prep: per-qubit gate matrices  mats[q] = Rx(w[3+q]) @ Rz(w[15+q])
// ---------------------------------------------------------------------------
__global__ void prep_kernel(const float* __restrict__ w) {
    int q = threadIdx.x;
    if (q < NQ) {
        float tx = 0.5f * w[3 + q];
        float tz = 0.5f * w[3 + NQ + q];
        float s, c, sz, cz;
        sincosf(tx, &s, &c);
        sincosf(tz, &sz, &cz);
        float* m = g_gates + q * 8;
        m[0] =  c * cz;  m[1] = -c * sz;
        m[2] =  s * sz;  m[3] = -s * cz;
        m[4] = -s * sz;  m[5] = -s * cz;
        m[6] =  c * cz;  m[7] =  c * sz;
    }
}

// ---------------------------------------------------------------------------
// split_EG: one pass over E producing Ehi/Elo (full) and Ghi/Glo (half).
// ---------------------------------------------------------------------------
__global__ __launch_bounds__(256) void split_EG(const float* __restrict__ E,
                                                const float* __restrict__ w) {
    float th  = 0.5f * (w[0] + w[1] + w[2]);
    float r00 = cosf(th);
    float r01 = -sinf(th);
    size_t i = (size_t)blockIdx.x * blockDim.x + threadIdx.x;   // float4 idx in top half
    const size_t HOFF4 = (size_t)HALFN * DIMN / 4;
    const float4* E4 = (const float4*)E;
    float4 a = E4[i];
    float4 b = E4[i + HOFF4];

    __nv_bfloat162* Eh2 = (__nv_bfloat162*)g_Eh;
    __nv_bfloat162* El2 = (__nv_bfloat162*)g_El;
    __nv_bfloat162* Gh2 = (__nv_bfloat162*)g_Gh;
    __nv_bfloat162* Gl2 = (__nv_bfloat162*)g_Gl;

    float va[4] = {a.x, a.y, a.z, a.w};
    float vb[4] = {b.x, b.y, b.z, b.w};
    __nv_bfloat16 eh[8], el[8], gh[4], gl[4];
    #pragma unroll
    for (int k = 0; k < 4; ++k) {
        split1(va[k], eh[k],     el[k]);
        split1(vb[k], eh[4 + k], el[4 + k]);
        float g = r00 * va[k] + r01 * vb[k];
        split1(g, gh[k], gl[k]);
    }
    size_t t2 = 2 * i;
    size_t b2 = 2 * (i + HOFF4);
    Eh2[t2]     = __nv_bfloat162(eh[0], eh[1]);
    Eh2[t2 + 1] = __nv_bfloat162(eh[2], eh[3]);
    El2[t2]     = __nv_bfloat162(el[0], el[1]);
    El2[t2 + 1] = __nv_bfloat162(el[2], el[3]);
    Eh2[b2]     = __nv_bfloat162(eh[4], eh[5]);
    Eh2[b2 + 1] = __nv_bfloat162(eh[6], eh[7]);
    El2[b2]     = __nv_bfloat162(el[4], el[5]);
    El2[b2 + 1] = __nv_bfloat162(el[6], el[7]);
    Gh2[t2]     = __nv_bfloat162(gh[0], gh[1]);
    Gh2[t2 + 1] = __nv_bfloat162(gh[2], gh[3]);
    Gl2[t2]     = __nv_bfloat162(gl[0], gl[1]);
    Gl2[t2 + 1] = __nv_bfloat162(gl[2], gl[3]);
}

// ---------------------------------------------------------------------------
// encode
// ---------------------------------------------------------------------------
__global__ __launch_bounds__(256) void encode_kernel(const float* __restrict__ inputs) {
    __shared__ float ar[NQ], ai[NQ], br[NQ], bi[NQ];
    const int b = blockIdx.x;
    if (threadIdx.x < NQ) {
        float x = inputs[b * NQ + threadIdx.x];
        float sy, cy, sz, cz;
        sincosf(0.5f * x, &sy, &cy);
        sincosf(0.5f * x * x, &sz, &cz);
        ar[threadIdx.x] = cy * cz;  ai[threadIdx.x] = -cy * sz;
        br[threadIdx.x] = sy * cz;  bi[threadIdx.x] =  sy * sz;
    }
    __syncthreads();
    for (int j = threadIdx.x; j < DIMN; j += blockDim.x) {
        float pr = 1.f, pi = 0.f;
        #pragma unroll
        for (int q = 0; q < NQ; ++q) {
            int bit = (j >> (NQ - 1 - q)) & 1;
            float cr = bit ? br[q] : ar[q];
            float ci = bit ? bi[q] : ai[q];
            float nr = pr * cr - pi * ci;
            float ni = pr * ci + pi * cr;
            pr = nr; pi = ni;
        }
        __nv_bfloat16 h, l;
        split1(pr, h, l);
        g_Ah[(size_t)b * DIMN + j] = h;
        g_Al[(size_t)b * DIMN + j] = l;
        split1(pi, h, l);
        g_Ah[(size_t)(NBATCH + b) * DIMN + j] = h;
        g_Al[(size_t)(NBATCH + b) * DIMN + j] = l;
    }
}

// ---------------------------------------------------------------------------
// Split-bf16 NT GEMM (mma.sync + ldmatrix):
//   C[M,N] = (Ah+Al)[M,K] * ((Bh+Bl)[N,K])^T,  acc = AhBh + AhBl + AlBh
// CTA tile 128x128, BK=32, 4-stage cp.async ring, 8 warps (warp 64x32).
// SMEM rows: 64B (32 bf16), 16B-chunk XOR swizzle: phys = j ^ ((row>>1)&3).
// Operands selected in-kernel from __device__ globals (host cannot pass
// device-symbol addresses as args).
// ---------------------------------------------------------------------------
#define BM 128
#define BN 128
#define BKC 32
#define STAGES 4
#define OAH 0
#define OAL 8192
#define OBH 16384
#define OBL 24576
#define STG 32768
#define DSMEM (STAGES * STG)   // 131072

__device__ __forceinline__ uint32_t smem_u32(const void* p) {
    return (uint32_t)__cvta_generic_to_shared(p);
}
__device__ __forceinline__ void cpa16u(uint32_t s, const void* g) {
    asm volatile("cp.async.cg.shared.global [%0], [%1], 16;" :: "r"(s), "l"(g));
}
__device__ __forceinline__ void ldsm4(uint32_t& r0, uint32_t& r1, uint32_t& r2,
                                      uint32_t& r3, uint32_t a) {
    asm volatile("ldmatrix.sync.aligned.m8n8.x4.shared.b16 {%0,%1,%2,%3}, [%4];"
                 : "=r"(r0), "=r"(r1), "=r"(r2), "=r"(r3) : "r"(a));
}
__device__ __forceinline__ void mma16(float c[4], const uint32_t a[4], const uint32_t b[2]) {
    asm volatile(
        "mma.sync.aligned.m16n8k16.row.col.f32.bf16.bf16.f32 "
        "{%0,%1,%2,%3}, {%4,%5,%6,%7}, {%8,%9}, {%0,%1,%2,%3};\n"
        : "+f"(c[0]), "+f"(c[1]), "+f"(c[2]), "+f"(c[3])
        : "r"(a[0]), "r"(a[1]), "r"(a[2]), "r"(a[3]), "r"(b[0]), "r"(b[1]));
}

// swizzled byte offset within a 64B-row tile
__device__ __forceinline__ uint32_t swz(int row, int chunk) {
    return (uint32_t)row * 64u + (uint32_t)((chunk ^ ((row >> 1) & 3)) << 4);
}

// load one BK=32 chunk of all four operand tiles into a stage
__device__ __forceinline__ void load_chunk(uint32_t sbase,
    const __nv_bfloat16* __restrict__ Ah, const __nv_bfloat16* __restrict__ Al,
    const __nv_bfloat16* __restrict__ Bh, const __nv_bfloat16* __restrict__ Bl,
    size_t aoff, size_t boff, int k0, int tid)
{
    const int r = tid >> 2;        // 0..63
    const int j = tid & 3;         // 16B chunk
    #pragma unroll
    for (int i = 0; i < 2; ++i) {
        int row = r + 64 * i;
        uint32_t so = swz(row, j);
        size_t go = aoff + (size_t)row * GK + k0 + j * 8;
        cpa16u(sbase + OAH + so, Ah + go);
        cpa16u(sbase + OAL + so, Al + go);
        size_t gob = boff + (size_t)row * GK + k0 + j * 8;
        cpa16u(sbase + OBH + so, Bh + gob);
        cpa16u(sbase + OBL + so, Bl + gob);
    }
}

__global__ void __launch_bounds__(256, 1)
gemm_split(int which) {
    extern __shared__ char dsm[];
    const uint32_t sb = smem_u32(dsm);
    const int tid  = threadIdx.x;
    const int warp = tid >> 5;
    const int lane = tid & 31;
    const int wm = (warp & 1) * 64;
    const int wn = (warp >> 1) * 32;

    const __nv_bfloat16* Ah = g_Ah;
    const __nv_bfloat16* Al = g_Al;
    const __nv_bfloat16* Bh = which ? g_Gh : g_Eh;
    const __nv_bfloat16* Bl = which ? g_Gl : g_El;
    float* C       = which ? g_Y : g_W;
    const int Ntot = which ? HALFN : DIMN;

    const size_t aoff = (size_t)blockIdx.y * BM * GK;
    const size_t boff = (size_t)blockIdx.x * BN * GK;

    // ldmatrix thread->row mapping
    const int q = lane >> 3;       // matrix index 0..3
    const int e = lane & 7;        // row within 8
    // A x4 matrices: (m0-7,c),(m8-15,c),(m0-7,c+1),(m8-15,c+1)
    int arow[4]; uint32_t aox[4];
    #pragma unroll
    for (int mt = 0; mt < 4; ++mt) {
        arow[mt] = wm + mt * 16 + e + (q & 1) * 8;
        aox[mt]  = (uint32_t)arow[mt] * 64u;
    }
    const int acs = q >> 1;        // chunk add for A mats
    // B x4 matrices: (n0-7,c),(n0-7,c+1),(n8-15,c),(n8-15,c+1)
    int brow[2];
    #pragma unroll
    for (int p = 0; p < 2; ++p)
        brow[p] = wn + p * 16 + e + (q >> 1) * 8;
    const int bcs = q & 1;         // chunk add for B mats

    float acc[4][4][4];
    #pragma unroll
    for (int i = 0; i < 4; ++i)
        #pragma unroll
        for (int jj = 0; jj < 4; ++jj)
            #pragma unroll
            for (int k = 0; k < 4; ++k) acc[i][jj][k] = 0.f;

    const int nk = GK / BKC;   // 128

    // prologue: chunks 0,1,2 -> stages 0,1,2
    #pragma unroll
    for (int s = 0; s < 3; ++s) {
        load_chunk(sb + s * STG, Ah, Al, Bh, Bl, aoff, boff, s * BKC, tid);
        asm volatile("cp.async.commit_group;" ::: "memory");
    }

    for (int it = 0; it < nk; ++it) {
        if (it < nk - 2)       asm volatile("cp.async.wait_group 2;" ::: "memory");
        else if (it == nk - 2) asm volatile("cp.async.wait_group 1;" ::: "memory");
        else                   asm volatile("cp.async.wait_group 0;" ::: "memory");
        __syncthreads();

        if (it + 3 < nk) {
            load_chunk(sb + ((it + 3) & 3) * STG, Ah, Al, Bh, Bl, aoff, boff,
                       (it + 3) * BKC, tid);
            asm volatile("cp.async.commit_group;" ::: "memory");
        }

        const uint32_t stg = sb + (uint32_t)(it & 3) * STG;
        #pragma unroll
        for (int ks = 0; ks < 2; ++ks) {
            const int c = 2 * ks;
            uint32_t afh[4][4], afl[4][4], bfh[2][4], bfl[2][4];
            #pragma unroll
            for (int mt = 0; mt < 4; ++mt) {
                uint32_t sx = (uint32_t)(((c + acs) ^ ((arow[mt] >> 1) & 3)) << 4);
                ldsm4(afh[mt][0], afh[mt][1], afh[mt][2], afh[mt][3],
                      stg + OAH + aox[mt] + sx);
                ldsm4(afl[mt][0], afl[mt][1], afl[mt][2], afl[mt][3],
                      stg + OAL + aox[mt] + sx);
            }
            #pragma unroll
            for (int p = 0; p < 2; ++p) {
                uint32_t sx = swz(brow[p], c + bcs);
                ldsm4(bfh[p][0], bfh[p][1], bfh[p][2], bfh[p][3], stg + OBH + sx);
                ldsm4(bfl[p][0], bfl[p][1], bfl[p][2], bfl[p][3], stg + OBL + sx);
            }
            #pragma unroll
            for (int mt = 0; mt < 4; ++mt)
                #pragma unroll
                for (int p = 0; p < 2; ++p) {
                    #pragma unroll
                    for (int h = 0; h < 2; ++h) {   // nt = 2p+h
                        mma16(acc[mt][2 * p + h], afh[mt], &bfh[p][2 * h]);
                        mma16(acc[mt][2 * p + h], afh[mt], &bfl[p][2 * h]);
                        mma16(acc[mt][2 * p + h], afl[mt], &bfh[p][2 * h]);
                    }
                }
        }
        __syncthreads();
    }

    // epilogue
    const int g  = lane >> 2;
    const int t4 = lane & 3;
    #pragma unroll
    for (int mt = 0; mt < 4; ++mt) {
        int row = blockIdx.y * BM + wm + mt * 16 + g;
        #pragma unroll
        for (int nt = 0; nt < 4; ++nt) {
            int col = blockIdx.x * BN + wn + nt * 8 + 2 * t4;
            float2 v0 = make_float2(acc[mt][nt][0], acc[mt][nt][1]);
            float2 v1 = make_float2(acc[mt][nt][2], acc[mt][nt][3]);
            *(float2*)&C[(size_t)row * Ntot + col]       = v0;
            *(float2*)&C[(size_t)(row + 8) * Ntot + col] = v1;
        }
    }
}

// ---------------------------------------------------------------------------
// gate sweep: apply 12 complex 2x2 gates per batch row in smem, write split bf16
// ---------------------------------------------------------------------------
__global__ __launch_bounds__(256) void gate_kernel() {
    __shared__ float wr[DIMN];
    __shared__ float wi[DIMN];
    const int b = blockIdx.x;
    const float* Wr = g_W + (size_t)b * DIMN;
    const float* Wi = g_W + (size_t)(NBATCH + b) * DIMN;

    for (int j = threadIdx.x * 4; j < DIMN; j += blockDim.x * 4) {
        *(float4*)&wr[j] = *(const float4*)&Wr[j];
        *(float4*)&wi[j] = *(const float4*)&Wi[j];
    }
    __syncthreads();

    #pragma unroll 1
    for (int q = 0; q < NQ; ++q) {
        const float* m = g_gates + q * 8;
        float m00r = m[0], m00i = m[1], m01r = m[2], m01i = m[3];
        float m10r = m[4], m10i = m[5], m11r = m[6], m11i = m[7];
        int p  = NQ - 1 - q;
        int st = 1 << p;
        for (int t = threadIdx.x; t < HALFN; t += blockDim.x) {
            int j0 = ((t >> p) << (p + 1)) | (t & (st - 1));
            int j1 = j0 + st;
            float w0r = wr[j0], w0i = wi[j0];
            float w1r = wr[j1], w1i = wi[j1];
            wr[j0] = m00r * w0r - m00i * w0i + m01r * w1r - m01i * w1i;
            wi[j0] = m00r * w0i + m00i * w0r + m01r * w1i + m01i * w1r;
            wr[j1] = m10r * w0r - m10i * w0i + m11r * w1r - m11i * w1i;
            wi[j1] = m10r * w0i + m10i * w0r + m11r * w1i + m11i * w1r;
        }
        __syncthreads();
    }

    for (int j = threadIdx.x; j < DIMN; j += blockDim.x) {
        __nv_bfloat16 h, l;
        split1(wr[j], h, l);
        g_Ah[(size_t)b * DIMN + j] = h;
        g_Al[(size_t)b * DIMN + j] = l;
        split1(wi[j], h, l);
        g_Ah[(size_t)(NBATCH + b) * DIMN + j] = h;
        g_Al[(size_t)(NBATCH + b) * DIMN + j] = l;
    }
}

// ---------------------------------------------------------------------------
// reduce: out[b] = sum_i Yr[b,i]^2 + Yi[b,i]^2
// ---------------------------------------------------------------------------
__global__ __launch_bounds__(256) void reduce_kernel(float* __restrict__ out) {
    const int b = blockIdx.x;
    const float* Yr = g_Y + (size_t)b * HALFN;
    const float* Yi = g_Y + (size_t)(NBATCH + b) * HALFN;
    float s = 0.f;
    for (int i = threadIdx.x; i < HALFN; i += blockDim.x) {
        float a = Yr[i], c = Yi[i];
        s += a * a + c * c;
    }
    #pragma unroll
    for (int o = 16; o > 0; o >>= 1) s += __shfl_xor_sync(0xffffffffu, s, o);
    __shared__ float red[8];
    if ((threadIdx.x & 31) == 0) red[threadIdx.x >> 5] = s;
    __syncthreads();
    if (threadIdx.x < 8) {
        s = red[threadIdx.x];
        #pragma unroll
        for (int o = 4; o > 0; o >>= 1) s += __shfl_xor_sync(0xffu, s, o);
        if (threadIdx.x == 0) out[b] = s;
    }
}

// ---------------------------------------------------------------------------
extern "C" void kernel_launch(void* const* d_in, const int* in_sizes, int n_in,
                              void* d_out, int out_size) {
    const float* inputs = (const float*)d_in[0];   // [2048,12]
    const float* weight = (const float*)d_in[1];   // [27]
    const float* E      = (const float*)d_in[2];   // [4096,4096]
    float* out          = (float*)d_out;           // [2048]

    cudaFuncSetAttribute(gemm_split, cudaFuncAttributeMaxDynamicSharedMemorySize,
                         DSMEM);

    prep_kernel<<<1, 32>>>(weight);
    split_EG<<<(HALFN * DIMN / 4) / 256, 256>>>(E, weight);
    encode_kernel<<<NBATCH, 256>>>(inputs);

    {
        dim3 grid(DIMN / BN, MROWS / BM);   // (32, 32)
        gemm_split<<<grid, 256, DSMEM>>>(0);
    }
    gate_kernel<<<NBATCH, 256>>>();
    {
        dim3 grid(HALFN / BN, MROWS / BM);  // (16, 32)
        gemm_split<<<grid, 256, DSMEM>>>(1);
    }
    reduce_kernel<<<NBATCH, 256>>>(out);
}

// round 6
// speedup vs baseline: 1.5188x; 1.1427x over previous
#include <cuda_runtime.h>
#include <cuda_bf16.h>
#include <math.h>
#include <stdint.h>

// Problem constants
#define NQ     12
#define DIMN   4096
#define HALFN  2048
#define NBATCH 2048
#define MROWS  (2 * NBATCH)   // stacked re/im rows = 4096
#define GK     4096           // GEMM K

// ---------------------------------------------------------------------------
// Scratch (__device__ globals per harness rules)
// ---------------------------------------------------------------------------
__device__ __nv_bfloat16 g_Ah[(size_t)MROWS * DIMN];   // V hi, later W hi
__device__ __nv_bfloat16 g_Al[(size_t)MROWS * DIMN];   // V lo, later W lo
__device__ __nv_bfloat16 g_Eh[(size_t)DIMN * DIMN];
__device__ __nv_bfloat16 g_El[(size_t)DIMN * DIMN];
__device__ __nv_bfloat16 g_Gh[(size_t)HALFN * DIMN];   // G = r00*Etop + r01*Ebot
__device__ __nv_bfloat16 g_Gl[(size_t)HALFN * DIMN];
__device__ float g_W[(size_t)MROWS * DIMN];            // GEMM1 output (fp32)
__device__ float g_Y[(size_t)MROWS * HALFN];           // GEMM2 output (fp32)
__device__ float g_gates[NQ * 8];

__device__ __forceinline__ void split1(float x, __nv_bfloat16& h, __nv_bfloat16& l) {
    h = __float2bfloat16(x);
    l = __float2bfloat16(x - __bfloat162float(h));
}

// ---------------------------------------------------------------------------
// prep: per-qubit gate matrices  mats[q] = Rx(w[3+q]) @ Rz(w[15+q])
// ---------------------------------------------------------------------------
__global__ void prep_kernel(const float* __restrict__ w) {
    int q = threadIdx.x;
    if (q < NQ) {
        float tx = 0.5f * w[3 + q];
        float tz = 0.5f * w[3 + NQ + q];
        float s, c, sz, cz;
        sincosf(tx, &s, &c);
        sincosf(tz, &sz, &cz);
        float* m = g_gates + q * 8;
        m[0] =  c * cz;  m[1] = -c * sz;
        m[2] =  s * sz;  m[3] = -s * cz;
        m[4] = -s * sz;  m[5] = -s * cz;
        m[6] =  c * cz;  m[7] =  c * sz;
    }
}

// ---------------------------------------------------------------------------
// split_EG: one pass over E producing Ehi/Elo (full) and Ghi/Glo (half).
// ---------------------------------------------------------------------------
__global__ __launch_bounds__(256) void split_EG(const float* __restrict__ E,
                                                const float* __restrict__ w) {
    float th  = 0.5f * (w[0] + w[1] + w[2]);
    float r00 = cosf(th);
    float r01 = -sinf(th);
    size_t i = (size_t)blockIdx.x * blockDim.x + threadIdx.x;   // float4 idx in top half
    const size_t HOFF4 = (size_t)HALFN * DIMN / 4;
    const float4* E4 = (const float4*)E;
    float4 a = E4[i];
    float4 b = E4[i + HOFF4];

    __nv_bfloat162* Eh2 = (__nv_bfloat162*)g_Eh;
    __nv_bfloat162* El2 = (__nv_bfloat162*)g_El;
    __nv_bfloat162* Gh2 = (__nv_bfloat162*)g_Gh;
    __nv_bfloat162* Gl2 = (__nv_bfloat162*)g_Gl;

    float va[4] = {a.x, a.y, a.z, a.w};
    float vb[4] = {b.x, b.y, b.z, b.w};
    __nv_bfloat16 eh[8], el[8], gh[4], gl[4];
    #pragma unroll
    for (int k = 0; k < 4; ++k) {
        split1(va[k], eh[k],     el[k]);
        split1(vb[k], eh[4 + k], el[4 + k]);
        float g = r00 * va[k] + r01 * vb[k];
        split1(g, gh[k], gl[k]);
    }
    size_t t2 = 2 * i;
    size_t b2 = 2 * (i + HOFF4);
    Eh2[t2]     = __nv_bfloat162(eh[0], eh[1]);
    Eh2[t2 + 1] = __nv_bfloat162(eh[2], eh[3]);
    El2[t2]     = __nv_bfloat162(el[0], el[1]);
    El2[t2 + 1] = __nv_bfloat162(el[2], el[3]);
    Eh2[b2]     = __nv_bfloat162(eh[4], eh[5]);
    Eh2[b2 + 1] = __nv_bfloat162(eh[6], eh[7]);
    El2[b2]     = __nv_bfloat162(el[4], el[5]);
    El2[b2 + 1] = __nv_bfloat162(el[6], el[7]);
    Gh2[t2]     = __nv_bfloat162(gh[0], gh[1]);
    Gh2[t2 + 1] = __nv_bfloat162(gh[2], gh[3]);
    Gl2[t2]     = __nv_bfloat162(gl[0], gl[1]);
    Gl2[t2 + 1] = __nv_bfloat162(gl[2], gl[3]);
}

// ---------------------------------------------------------------------------
// encode
// ---------------------------------------------------------------------------
__global__ __launch_bounds__(256) void encode_kernel(const float* __restrict__ inputs) {
    __shared__ float ar[NQ], ai[NQ], br[NQ], bi[NQ];
    const int b = blockIdx.x;
    if (threadIdx.x < NQ) {
        float x = inputs[b * NQ + threadIdx.x];
        float sy, cy, sz, cz;
        sincosf(0.5f * x, &sy, &cy);
        sincosf(0.5f * x * x, &sz, &cz);
        ar[threadIdx.x] = cy * cz;  ai[threadIdx.x] = -cy * sz;
        br[threadIdx.x] = sy * cz;  bi[threadIdx.x] =  sy * sz;
    }
    __syncthreads();
    for (int j = threadIdx.x; j < DIMN; j += blockDim.x) {
        float pr = 1.f, pi = 0.f;
        #pragma unroll
        for (int q = 0; q < NQ; ++q) {
            int bit = (j >> (NQ - 1 - q)) & 1;
            float cr = bit ? br[q] : ar[q];
            float ci = bit ? bi[q] : ai[q];
            float nr = pr * cr - pi * ci;
            float ni = pr * ci + pi * cr;
            pr = nr; pi = ni;
        }
        __nv_bfloat16 h, l;
        split1(pr, h, l);
        g_Ah[(size_t)b * DIMN + j] = h;
        g_Al[(size_t)b * DIMN + j] = l;
        split1(pi, h, l);
        g_Ah[(size_t)(NBATCH + b) * DIMN + j] = h;
        g_Al[(size_t)(NBATCH + b) * DIMN + j] = l;
    }
}

// ---------------------------------------------------------------------------
// Split-bf16 NT GEMM (mma.sync + ldmatrix):
//   C[M,N] = (Ah+Al)[M,K] * ((Bh+Bl)[N,K])^T,  acc = AhBh + AhBl + AlBh
// CTA tile 128x128, BK=32, 3-stage cp.async ring, 8 warps (warp 64x32),
// 2 CTAs/SM (96KB smem each, 128-reg cap). One __syncthreads per chunk.
// SMEM rows: 64B (32 bf16), 16B-chunk XOR swizzle: phys = j ^ ((row>>1)&3).
// ---------------------------------------------------------------------------
#define BM 128
#define BN 128
#define BKC 32
#define STAGES 3
#define OAH 0
#define OAL 8192
#define OBH 16384
#define OBL 24576
#define STG 32768
#define DSMEM (STAGES * STG)   // 98304

__device__ __forceinline__ uint32_t smem_u32(const void* p) {
    return (uint32_t)__cvta_generic_to_shared(p);
}
__device__ __forceinline__ void cpa16u(uint32_t s, const void* g) {
    asm volatile("cp.async.cg.shared.global [%0], [%1], 16;" :: "r"(s), "l"(g));
}
__device__ __forceinline__ void ldsm4(uint32_t& r0, uint32_t& r1, uint32_t& r2,
                                      uint32_t& r3, uint32_t a) {
    asm volatile("ldmatrix.sync.aligned.m8n8.x4.shared.b16 {%0,%1,%2,%3}, [%4];"
                 : "=r"(r0), "=r"(r1), "=r"(r2), "=r"(r3) : "r"(a));
}
__device__ __forceinline__ void mma16(float c[4], const uint32_t a[4], const uint32_t b[2]) {
    asm volatile(
        "mma.sync.aligned.m16n8k16.row.col.f32.bf16.bf16.f32 "
        "{%0,%1,%2,%3}, {%4,%5,%6,%7}, {%8,%9}, {%0,%1,%2,%3};\n"
        : "+f"(c[0]), "+f"(c[1]), "+f"(c[2]), "+f"(c[3])
        : "r"(a[0]), "r"(a[1]), "r"(a[2]), "r"(a[3]), "r"(b[0]), "r"(b[1]));
}

// swizzled byte offset within a 64B-row tile
__device__ __forceinline__ uint32_t swz(int row, int chunk) {
    return (uint32_t)row * 64u + (uint32_t)((chunk ^ ((row >> 1) & 3)) << 4);
}

// load one BK=32 chunk of all four operand tiles into a stage
__device__ __forceinline__ void load_chunk(uint32_t sbase,
    const __nv_bfloat16* __restrict__ Ah, const __nv_bfloat16* __restrict__ Al,
    const __nv_bfloat16* __restrict__ Bh, const __nv_bfloat16* __restrict__ Bl,
    size_t aoff, size_t boff, int k0, int tid)
{
    const int r = tid >> 2;        // 0..63
    const int j = tid & 3;         // 16B chunk
    #pragma unroll
    for (int i = 0; i < 2; ++i) {
        int row = r + 64 * i;
        uint32_t so = swz(row, j);
        size_t go = aoff + (size_t)row * GK + k0 + j * 8;
        cpa16u(sbase + OAH + so, Ah + go);
        cpa16u(sbase + OAL + so, Al + go);
        size_t gob = boff + (size_t)row * GK + k0 + j * 8;
        cpa16u(sbase + OBH + so, Bh + gob);
        cpa16u(sbase + OBL + so, Bl + gob);
    }
}

__global__ void __launch_bounds__(256, 2)
gemm_split(int which) {
    extern __shared__ char dsm[];
    const uint32_t sb = smem_u32(dsm);
    const int tid  = threadIdx.x;
    const int warp = tid >> 5;
    const int lane = tid & 31;
    const int wm = (warp & 1) * 64;
    const int wn = (warp >> 1) * 32;

    const __nv_bfloat16* Ah = g_Ah;
    const __nv_bfloat16* Al = g_Al;
    const __nv_bfloat16* Bh = which ? g_Gh : g_Eh;
    const __nv_bfloat16* Bl = which ? g_Gl : g_El;
    float* C       = which ? g_Y : g_W;
    const int Ntot = which ? HALFN : DIMN;

    const size_t aoff = (size_t)blockIdx.y * BM * GK;
    const size_t boff = (size_t)blockIdx.x * BN * GK;

    // ldmatrix thread->row mapping
    const int q = lane >> 3;       // matrix index 0..3
    const int e = lane & 7;        // row within 8
    // A x4 matrices: (m0-7,c),(m8-15,c),(m0-7,c+1),(m8-15,c+1)
    int arow[4]; uint32_t aox[4];
    #pragma unroll
    for (int mt = 0; mt < 4; ++mt) {
        arow[mt] = wm + mt * 16 + e + (q & 1) * 8;
        aox[mt]  = (uint32_t)arow[mt] * 64u;
    }
    const int acs = q >> 1;        // chunk add for A mats
    // B x4 matrices: (n0-7,c),(n0-7,c+1),(n8-15,c),(n8-15,c+1)
    int brow[2];
    #pragma unroll
    for (int p = 0; p < 2; ++p)
        brow[p] = wn + p * 16 + e + (q >> 1) * 8;
    const int bcs = q & 1;         // chunk add for B mats

    float acc[4][4][4];
    #pragma unroll
    for (int i = 0; i < 4; ++i)
        #pragma unroll
        for (int jj = 0; jj < 4; ++jj)
            #pragma unroll
            for (int k = 0; k < 4; ++k) acc[i][jj][k] = 0.f;

    const int nk = GK / BKC;   // 128

    // prologue: chunks 0,1 -> stages 0,1
    #pragma unroll
    for (int s = 0; s < 2; ++s) {
        load_chunk(sb + s * STG, Ah, Al, Bh, Bl, aoff, boff, s * BKC, tid);
        asm volatile("cp.async.commit_group;" ::: "memory");
    }

    int stage = 0;
    for (int it = 0; it < nk; ++it) {
        if (it + 1 < nk) asm volatile("cp.async.wait_group 1;" ::: "memory");
        else             asm volatile("cp.async.wait_group 0;" ::: "memory");
        __syncthreads();

        if (it + 2 < nk) {
            int ns = stage + 2; if (ns >= STAGES) ns -= STAGES;
            load_chunk(sb + ns * STG, Ah, Al, Bh, Bl, aoff, boff,
                       (it + 2) * BKC, tid);
            asm volatile("cp.async.commit_group;" ::: "memory");
        }

        const uint32_t stg = sb + (uint32_t)stage * STG;
        #pragma unroll
        for (int ks = 0; ks < 2; ++ks) {
            const int c = 2 * ks;
            uint32_t afh[4][4], afl[4][4], bfh[2][4], bfl[2][4];
            #pragma unroll
            for (int mt = 0; mt < 4; ++mt) {
                uint32_t sx = (uint32_t)(((c + acs) ^ ((arow[mt] >> 1) & 3)) << 4);
                ldsm4(afh[mt][0], afh[mt][1], afh[mt][2], afh[mt][3],
                      stg + OAH + aox[mt] + sx);
                ldsm4(afl[mt][0], afl[mt][1], afl[mt][2], afl[mt][3],
                      stg + OAL + aox[mt] + sx);
            }
            #pragma unroll
            for (int p = 0; p < 2; ++p) {
                uint32_t sx = swz(brow[p], c + bcs);
                ldsm4(bfh[p][0], bfh[p][1], bfh[p][2], bfh[p][3], stg + OBH + sx);
                ldsm4(bfl[p][0], bfl[p][1], bfl[p][2], bfl[p][3], stg + OBL + sx);
            }
            // term-major ordering: consecutive MMAs hit different accumulators
            #pragma unroll
            for (int mt = 0; mt < 4; ++mt)
                #pragma unroll
                for (int p = 0; p < 2; ++p)
                    #pragma unroll
                    for (int h = 0; h < 2; ++h)
                        mma16(acc[mt][2 * p + h], afh[mt], &bfh[p][2 * h]);
            #pragma unroll
            for (int mt = 0; mt < 4; ++mt)
                #pragma unroll
                for (int p = 0; p < 2; ++p)
                    #pragma unroll
                    for (int h = 0; h < 2; ++h)
                        mma16(acc[mt][2 * p + h], afh[mt], &bfl[p][2 * h]);
            #pragma unroll
            for (int mt = 0; mt < 4; ++mt)
                #pragma unroll
                for (int p = 0; p < 2; ++p)
                    #pragma unroll
                    for (int h = 0; h < 2; ++h)
                        mma16(acc[mt][2 * p + h], afl[mt], &bfh[p][2 * h]);
        }
        if (++stage >= STAGES) stage = 0;
    }

    // epilogue
    const int g  = lane >> 2;
    const int t4 = lane & 3;
    #pragma unroll
    for (int mt = 0; mt < 4; ++mt) {
        int row = blockIdx.y * BM + wm + mt * 16 + g;
        #pragma unroll
        for (int nt = 0; nt < 4; ++nt) {
            int col = blockIdx.x * BN + wn + nt * 8 + 2 * t4;
            float2 v0 = make_float2(acc[mt][nt][0], acc[mt][nt][1]);
            float2 v1 = make_float2(acc[mt][nt][2], acc[mt][nt][3]);
            *(float2*)&C[(size_t)row * Ntot + col]       = v0;
            *(float2*)&C[(size_t)(row + 8) * Ntot + col] = v1;
        }
    }
}

// ---------------------------------------------------------------------------
// gate sweep: apply 12 complex 2x2 gates per batch row in smem, write split bf16
// ---------------------------------------------------------------------------
__global__ __launch_bounds__(256) void gate_kernel() {
    __shared__ float wr[DIMN];
    __shared__ float wi[DIMN];
    const int b = blockIdx.x;
    const float* Wr = g_W + (size_t)b * DIMN;
    const float* Wi = g_W + (size_t)(NBATCH + b) * DIMN;

    for (int j = threadIdx.x * 4; j < DIMN; j += blockDim.x * 4) {
        *(float4*)&wr[j] = *(const float4*)&Wr[j];
        *(float4*)&wi[j] = *(const float4*)&Wi[j];
    }
    __syncthreads();

    #pragma unroll 1
    for (int q = 0; q < NQ; ++q) {
        const float* m = g_gates + q * 8;
        float m00r = m[0], m00i = m[1], m01r = m[2], m01i = m[3];
        float m10r = m[4], m10i = m[5], m11r = m[6], m11i = m[7];
        int p  = NQ - 1 - q;
        int st = 1 << p;
        for (int t = threadIdx.x; t < HALFN; t += blockDim.x) {
            int j0 = ((t >> p) << (p + 1)) | (t & (st - 1));
            int j1 = j0 + st;
            float w0r = wr[j0], w0i = wi[j0];
            float w1r = wr[j1], w1i = wi[j1];
            wr[j0] = m00r * w0r - m00i * w0i + m01r * w1r - m01i * w1i;
            wi[j0] = m00r * w0i + m00i * w0r + m01r * w1i + m01i * w1r;
            wr[j1] = m10r * w0r - m10i * w0i + m11r * w1r - m11i * w1i;
            wi[j1] = m10r * w0i + m10i * w0r + m11r * w1i + m11i * w1r;
        }
        __syncthreads();
    }

    for (int j = threadIdx.x; j < DIMN; j += blockDim.x) {
        __nv_bfloat16 h, l;
        split1(wr[j], h, l);
        g_Ah[(size_t)b * DIMN + j] = h;
        g_Al[(size_t)b * DIMN + j] = l;
        split1(wi[j], h, l);
        g_Ah[(size_t)(NBATCH + b) * DIMN + j] = h;
        g_Al[(size_t)(NBATCH + b) * DIMN + j] = l;
    }
}

// ---------------------------------------------------------------------------
// reduce: out[b] = sum_i Yr[b,i]^2 + Yi[b,i]^2
// ---------------------------------------------------------------------------
__global__ __launch_bounds__(256) void reduce_kernel(float* __restrict__ out) {
    const int b = blockIdx.x;
    const float* Yr = g_Y + (size_t)b * HALFN;
    const float* Yi = g_Y + (size_t)(NBATCH + b) * HALFN;
    float s = 0.f;
    for (int i = threadIdx.x; i < HALFN; i += blockDim.x) {
        float a = Yr[i], c = Yi[i];
        s += a * a + c * c;
    }
    #pragma unroll
    for (int o = 16; o > 0; o >>= 1) s += __shfl_xor_sync(0xffffffffu, s, o);
    __shared__ float red[8];
    if ((threadIdx.x & 31) == 0) red[threadIdx.x >> 5] = s;
    __syncthreads();
    if (threadIdx.x < 8) {
        s = red[threadIdx.x];
        #pragma unroll
        for (int o = 4; o > 0; o >>= 1) s += __shfl_xor_sync(0xffu, s, o);
        if (threadIdx.x == 0) out[b] = s;
    }
}

// ---------------------------------------------------------------------------
extern "C" void kernel_launch(void* const* d_in, const int* in_sizes, int n_in,
                              void* d_out, int out_size) {
    const float* inputs = (const float*)d_in[0];   // [2048,12]
    const float* weight = (const float*)d_in[1];   // [27]
    const float* E      = (const float*)d_in[2];   // [4096,4096]
    float* out          = (float*)d_out;           // [2048]

    cudaFuncSetAttribute(gemm_split, cudaFuncAttributeMaxDynamicSharedMemorySize,
                         DSMEM);

    prep_kernel<<<1, 32>>>(weight);
    split_EG<<<(HALFN * DIMN / 4) / 256, 256>>>(E, weight);
    encode_kernel<<<NBATCH, 256>>>(inputs);

    {
        dim3 grid(DIMN / BN, MROWS / BM);   // (32, 32)
        gemm_split<<<grid, 256, DSMEM>>>(0);
    }
    gate_kernel<<<NBATCH, 256>>>();
    {
        dim3 grid(HALFN / BN, MROWS / BM);  // (16, 32)
        gemm_split<<<grid, 256, DSMEM>>>(1);
    }
    reduce_kernel<<<NBATCH, 256>>>(out);
}